// round 14
// baseline (speedup 1.0000x reference)
#include <cuda_runtime.h>
#include <cstdint>

// Complex attention, single-pass TF32 mma.m16n8k8. B=8 H=8 S=1024 D=64.
// R14: permuted-column smem layout -> LDS.64 fragment loads (half the LDS
// instructions); PAD=72 (conflict-free for both A- and B-access patterns).
// K1: attn=(q/8).k -> spill + per-(row,ktile) mag^2 min/max  [128q x 64k]
// K2: row min/max reduce
// K3: normalize(attn) @ v                                    [128q x 64d]

#define NKT 16
typedef unsigned long long u64;
typedef uint32_t u32;

__device__ float g_ar[(size_t)64 * 1024 * 1024];   // 256 MB
__device__ float g_ai[(size_t)64 * 1024 * 1024];   // 256 MB
__device__ float g_pmin[64 * 1024 * NKT];
__device__ float g_pmax[64 * 1024 * NKT];
__device__ float g_mn[64 * 1024];
__device__ float g_inv[64 * 1024];

#define PAD 72               // u32 per row; 72 % 32 == 8 -> conflict-free
#define NEGF 0x80000000u
#define QW (128 * PAD)
#define KW (64 * PAD)
// column permutation: logical col c -> storage slot; makes (tg, tg+4) adjacent
#define PCOL(c) (((c) & ~7) + (((c) & 3) << 1) + (((c) >> 2) & 1))

__device__ __forceinline__ u32 tf32c(float x) {
    u32 r; asm("cvt.rna.tf32.f32 %0, %1;" : "=r"(r) : "f"(x)); return r;
}
__device__ __forceinline__ u64 pk2(u32 lo, u32 hi) {
    return (u64)lo | ((u64)hi << 32);
}
__device__ __forceinline__ void mma_tf32(float* c, const u32* a, const u32* b) {
    asm volatile("mma.sync.aligned.m16n8k8.row.col.f32.tf32.tf32.f32 "
        "{%0,%1,%2,%3}, {%4,%5,%6,%7}, {%8,%9}, {%0,%1,%2,%3};"
        : "+f"(c[0]), "+f"(c[1]), "+f"(c[2]), "+f"(c[3])
        : "r"(a[0]), "r"(a[1]), "r"(a[2]), "r"(a[3]), "r"(b[0]), "r"(b[1]));
}

// A fragment via 2 x LDS.64 from permuted layout:
// u64 @ (row, 8kb+2tg) -> {a0=(row,tg+8kb), a2=(row,tg+4+8kb)}; row+8 -> a1,a3
__device__ __forceinline__ void ldA64(u32* a, const u32* base, int row, int off) {
    u64 t0 = *(const u64*)(base + row * PAD + off);
    u64 t1 = *(const u64*)(base + (row + 8) * PAD + off);
    a[0] = (u32)t0; a[2] = (u32)(t0 >> 32);
    a[1] = (u32)t1; a[3] = (u32)(t1 >> 32);
}

// ---------------------------------------------------------------------------
// K1: QK. CTA tile 128q x 64k, 8 warps (4m x 2n), warp tile 32q x 32k.
// Q,K stored in permuted-column tf32 layout. 2 CTAs/SM.
// attn_r = qr.kr - qi.ki ; attn_i = qr.ki + qi.kr  (negation via sign XOR)
// ---------------------------------------------------------------------------
__global__ __launch_bounds__(256, 2) void qk_kernel(
    const float* __restrict__ qr, const float* __restrict__ qi,
    const float* __restrict__ kr, const float* __restrict__ ki)
{
    extern __shared__ __align__(16) u32 sm[];
    u32* Qr = sm;                 // [128][PAD] permuted cols
    u32* Qi = Qr + QW;
    u32* Kr = Qi + QW;            // [64][PAD] permuted cols
    u32* Ki = Kr + KW;
    __shared__ float sMin[128][2], sMax[128][2];

    const int tid = threadIdx.x, wid = tid >> 5, lane = tid & 31;
    const int kt = blockIdx.x, qt = blockIdx.y, bh = blockIdx.z;
    const int fr = tid >> 5, l = tid & 31;
    const int p0 = PCOL(2 * l), p1 = PCOL(2 * l + 1);

    // ---- fill (LDG.64 coalesced; 2x STS.32 to permuted slots) ----
    {
        const size_t qbase = ((size_t)((bh << 10) + (qt << 7))) << 6;
        const size_t kbase = ((size_t)((bh << 10) + (kt << 6))) << 6;
        #pragma unroll
        for (int it = 0; it < 16; ++it) {
            int row = fr + (it << 3);
            float2 a = *(const float2*)(qr + qbase + (row << 6) + 2 * l);
            float2 b = *(const float2*)(qi + qbase + (row << 6) + 2 * l);
            Qr[row * PAD + p0] = tf32c(a.x * 0.125f);
            Qr[row * PAD + p1] = tf32c(a.y * 0.125f);
            Qi[row * PAD + p0] = tf32c(b.x * 0.125f);
            Qi[row * PAD + p1] = tf32c(b.y * 0.125f);
        }
        #pragma unroll
        for (int it = 0; it < 8; ++it) {
            int row = fr + (it << 3);
            float2 c = *(const float2*)(kr + kbase + (row << 6) + 2 * l);
            float2 d = *(const float2*)(ki + kbase + (row << 6) + 2 * l);
            Kr[row * PAD + p0] = tf32c(c.x);
            Kr[row * PAD + p1] = tf32c(c.y);
            Ki[row * PAD + p0] = tf32c(d.x);
            Ki[row * PAD + p1] = tf32c(d.y);
        }
    }
    __syncthreads();

    // ---- compute ----
    const int wm = wid >> 1, wn = wid & 1;
    const int g = lane >> 2, tg = lane & 3;
    float accR[2][4][4] = {}, accI[2][4][4] = {};

    #pragma unroll
    for (int kb = 0; kb < 8; ++kb) {
        const int off = kb * 8 + 2 * tg;
        u32 aqr[2][4], aqi[2][4];
        #pragma unroll
        for (int mb = 0; mb < 2; ++mb) {
            int row = wm * 32 + mb * 16 + g;
            ldA64(aqr[mb], Qr, row, off);
            ldA64(aqi[mb], Qi, row, off);
        }
        #pragma unroll
        for (int nb = 0; nb < 4; ++nb) {
            int n0 = wn * 32 + nb * 8 + g;
            u64 tr = *(const u64*)(Kr + n0 * PAD + off);
            u64 ti = *(const u64*)(Ki + n0 * PAD + off);
            u32 bkr[2] = { (u32)tr, (u32)(tr >> 32) };
            u32 bki[2] = { (u32)ti, (u32)(ti >> 32) };
            u32 bkn[2] = { bki[0] ^ NEGF, bki[1] ^ NEGF };
            #pragma unroll
            for (int mb = 0; mb < 2; ++mb) {
                mma_tf32(accR[mb][nb], aqr[mb], bkr);
                mma_tf32(accR[mb][nb], aqi[mb], bkn);
                mma_tf32(accI[mb][nb], aqr[mb], bki);
                mma_tf32(accI[mb][nb], aqi[mb], bkr);
            }
        }
    }

    // ---- epilogue: store attn + row mag^2 min/max ----
    #pragma unroll
    for (int mb = 0; mb < 2; ++mb)
        #pragma unroll
        for (int half = 0; half < 2; ++half) {
            int rl = wm * 32 + mb * 16 + half * 8 + g;
            size_t ab = (((size_t)((bh << 10) + (qt << 7) + rl)) << 10)
                      + (kt << 6) + wn * 32 + tg * 2;
            float mn = 3.4e38f, mx = 0.0f;
            #pragma unroll
            for (int nb = 0; nb < 4; ++nb) {
                float x0 = accR[mb][nb][half * 2], x1 = accR[mb][nb][half * 2 + 1];
                float y0 = accI[mb][nb][half * 2], y1 = accI[mb][nb][half * 2 + 1];
                *(float2*)(g_ar + ab + nb * 8) = make_float2(x0, x1);
                *(float2*)(g_ai + ab + nb * 8) = make_float2(y0, y1);
                float m0 = x0 * x0 + y0 * y0, m1 = x1 * x1 + y1 * y1;
                mn = fminf(mn, fminf(m0, m1));
                mx = fmaxf(mx, fmaxf(m0, m1));
            }
            mn = fminf(mn, __shfl_xor_sync(0xffffffffu, mn, 1));
            mn = fminf(mn, __shfl_xor_sync(0xffffffffu, mn, 2));
            mx = fmaxf(mx, __shfl_xor_sync(0xffffffffu, mx, 1));
            mx = fmaxf(mx, __shfl_xor_sync(0xffffffffu, mx, 2));
            if (tg == 0) { sMin[rl][wn] = mn; sMax[rl][wn] = mx; }
        }
    __syncthreads();
    if (tid < 128) {
        float mn = fminf(sMin[tid][0], sMin[tid][1]);
        float mx = fmaxf(sMax[tid][0], sMax[tid][1]);
        int row = (qt << 7) + tid;
        g_pmin[((bh << 10) + row) * NKT + kt] = mn;
        g_pmax[((bh << 10) + row) * NKT + kt] = mx;
    }
}

// ---------------------------------------------------------------------------
// K2: reduce 16 partials/row -> mn = sqrt(min m2), inv = 1/(mx - mn).
// ---------------------------------------------------------------------------
__global__ void minmax_kernel()
{
    int r = blockIdx.x * 256 + threadIdx.x;   // 65536 rows
    float mn2 = g_pmin[r * NKT], mx2 = g_pmax[r * NKT];
    #pragma unroll
    for (int t = 1; t < NKT; t++) {
        mn2 = fminf(mn2, g_pmin[r * NKT + t]);
        mx2 = fmaxf(mx2, g_pmax[r * NKT + t]);
    }
    float mnv = sqrtf(mn2), mxv = sqrtf(mx2);
    g_mn[r] = mnv;
    g_inv[r] = 1.0f / (mxv - mnv);
}

// ---------------------------------------------------------------------------
// K3: AV. CTA tile 128q x 64d; 16 k-chunks of 64. 8 warps (4m x 2n),
// warp tile 32q x 32d. A = normalized attn (permuted cols); V natural
// [64k][PAD] (no perm: B frag regs span rows; PAD=72 -> conflict-free).
// out_r = ar.vr - ai.vi ; out_i = ar.vi + ai.vr
// ---------------------------------------------------------------------------
__global__ __launch_bounds__(256, 2) void av_kernel(
    const float* __restrict__ vr, const float* __restrict__ vi,
    float* __restrict__ out)
{
    extern __shared__ __align__(16) u32 sm[];
    u32* Ar = sm;                 // [128][PAD] permuted cols
    u32* Ai = Ar + QW;
    u32* Vr = Ai + QW;            // [64][PAD] natural cols
    u32* Vi = Vr + KW;
    __shared__ float smn[128], sinv[128];

    const int tid = threadIdx.x, wid = tid >> 5, lane = tid & 31;
    const int qt = blockIdx.x, bh = blockIdx.y;
    const int fr = tid >> 5, l = tid & 31;
    const int p0 = PCOL(2 * l), p1 = PCOL(2 * l + 1);

    if (tid < 128) {
        int r = (bh << 10) + (qt << 7) + tid;
        float mnv = g_mn[r], invv = g_inv[r];
        sinv[tid] = invv;
        smn[tid] = mnv * invv;   // pre-multiplied
    }
    __syncthreads();

    const int wm = wid >> 1, wn = wid & 1;
    const int g = lane >> 2, tg = lane & 3;
    float accR[2][4][4] = {}, accI[2][4][4] = {};

    const size_t abase = ((size_t)((bh << 10) + (qt << 7))) << 10;
    const size_t vbase = ((size_t)(bh << 10)) << 6;

    for (int c = 0; c < 16; ++c) {
        // A fill: normalized attn [128q][64k] -> tf32 permuted
        #pragma unroll
        for (int it = 0; it < 16; ++it) {
            int row = fr + (it << 3);
            size_t ao = abase + ((size_t)row << 10) + (c << 6) + 2 * l;
            float2 a = *(const float2*)(g_ar + ao);
            float2 b = *(const float2*)(g_ai + ao);
            float invv = sinv[row], mni = smn[row];
            float f0 = invv - mni * rsqrtf(a.x * a.x + b.x * b.x);
            float f1 = invv - mni * rsqrtf(a.y * a.y + b.y * b.y);
            Ar[row * PAD + p0] = tf32c(a.x * f0);
            Ar[row * PAD + p1] = tf32c(a.y * f1);
            Ai[row * PAD + p0] = tf32c(b.x * f0);
            Ai[row * PAD + p1] = tf32c(b.y * f1);
        }
        // V fill: natural [64k][64d] -> tf32 (STS.64, conflict-free)
        #pragma unroll
        for (int it = 0; it < 8; ++it) {
            int krow = fr + (it << 3);
            size_t vo = vbase + ((size_t)((c << 6) + krow) << 6) + 2 * l;
            float2 x = *(const float2*)(vr + vo);
            float2 y = *(const float2*)(vi + vo);
            *(u64*)(Vr + krow * PAD + 2 * l) = pk2(tf32c(x.x), tf32c(x.y));
            *(u64*)(Vi + krow * PAD + 2 * l) = pk2(tf32c(y.x), tf32c(y.y));
        }
        __syncthreads();

        #pragma unroll
        for (int kb = 0; kb < 8; ++kb) {
            const int off = kb * 8 + 2 * tg;
            const int kc = kb * 8 + tg;
            u32 aar[2][4], aai[2][4];
            #pragma unroll
            for (int mb = 0; mb < 2; ++mb) {
                int row = wm * 32 + mb * 16 + g;
                ldA64(aar[mb], Ar, row, off);
                ldA64(aai[mb], Ai, row, off);
            }
            #pragma unroll
            for (int nb = 0; nb < 4; ++nb) {
                int n0 = wn * 32 + nb * 8 + g;
                u32 bvr[2], bvi[2], bvn[2];
                bvr[0] = Vr[kc * PAD + n0];       bvr[1] = Vr[(kc + 4) * PAD + n0];
                bvi[0] = Vi[kc * PAD + n0];       bvi[1] = Vi[(kc + 4) * PAD + n0];
                bvn[0] = bvi[0] ^ NEGF;           bvn[1] = bvi[1] ^ NEGF;
                #pragma unroll
                for (int mb = 0; mb < 2; ++mb) {
                    mma_tf32(accR[mb][nb], aar[mb], bvr);
                    mma_tf32(accR[mb][nb], aai[mb], bvn);
                    mma_tf32(accI[mb][nb], aar[mb], bvi);
                    mma_tf32(accI[mb][nb], aai[mb], bvr);
                }
            }
        }
        __syncthreads();
    }

    // ---- epilogue: out[2][64][1024][64], imag at +4194304 ----
    #pragma unroll
    for (int mb = 0; mb < 2; ++mb)
        #pragma unroll
        for (int half = 0; half < 2; ++half) {
            int row = (qt << 7) + wm * 32 + mb * 16 + half * 8 + g;
            int d = wn * 32 + tg * 2;
            size_t ob = ((size_t)((bh << 10) + row) << 6) + d;
            #pragma unroll
            for (int nb = 0; nb < 4; ++nb) {
                *(float2*)(out + ob + nb * 8) =
                    make_float2(accR[mb][nb][half * 2], accR[mb][nb][half * 2 + 1]);
                *(float2*)(out + ob + nb * 8 + 4194304) =
                    make_float2(accI[mb][nb][half * 2], accI[mb][nb][half * 2 + 1]);
            }
        }
}

extern "C" void kernel_launch(void* const* d_in, const int* in_sizes, int n_in,
                              void* d_out, int out_size)
{
    (void)in_sizes; (void)n_in; (void)out_size;
    const float* qr = (const float*)d_in[0];
    const float* qi = (const float*)d_in[1];
    const float* kr = (const float*)d_in[2];
    const float* ki = (const float*)d_in[3];
    const float* vr = (const float*)d_in[4];
    const float* vi = (const float*)d_in[5];
    float* out = (float*)d_out;

    const int smem = (2 * QW + 2 * KW) * 4;   // 110592 B
    cudaFuncSetAttribute(qk_kernel, cudaFuncAttributeMaxDynamicSharedMemorySize, smem);
    cudaFuncSetAttribute(av_kernel, cudaFuncAttributeMaxDynamicSharedMemorySize, smem);

    qk_kernel<<<dim3(16, 8, 64), 256, smem>>>(qr, qi, kr, ki);
    minmax_kernel<<<256, 256>>>();
    av_kernel<<<dim3(8, 64), 256, smem>>>(vr, vi, out);
}